// round 10
// baseline (speedup 1.0000x reference)
#include <cuda_runtime.h>
#include <math.h>
#include <cstdint>

// ---------------- problem constants ----------------
#define BQ   4096
#define NU   100000
#define DIM  128
#define TOPK 5
#define K1   6
#define NSPLIT 4
#define NPS   25000                    // users per split
#define TM 128                         // queries per CTA
#define TN 128                         // users per tile
#define QB (BQ / TM)                   // 32
#define NTILES ((NPS + TN - 1) / TN)   // 196 (last tile: 40 valid, 88 pad)
#define PADROWS (NTILES * TN - NPS)    // 88
#define CAND 12
#define NCAND (NSPLIT * CAND)          // 48
#define SP_U32 132                     // sims pitch in u32 (multiple of 4 -> int4-aligned rows)
#define INT_MIN_V (-2147483647 - 1)

// ---------------- device scratch -------------------------------------------
__device__ float    g_ue_n[(size_t)NU * DIM];
__device__ float    g_q_n[(size_t)BQ * DIM];
// per (split, tile): u32[32 kq][128 n] panel (16KB, contiguous)
__device__ uint32_t g_ubsw[(size_t)NSPLIT * NTILES * 4096];
// per q-block: u32[32 kq][128 m] panel
__device__ uint32_t g_qa[(size_t)QB * 4096];
__device__ int      g_ci[(size_t)BQ * NCAND];

// ---------------- helpers ---------------------------------------------------
static __device__ __forceinline__ uint32_t smem_u32(const void* p) {
    uint32_t a;
    asm("{ .reg .u64 t; cvta.to.shared.u64 t, %1; cvt.u32.u64 %0, t; }" : "=r"(a) : "l"(p));
    return a;
}
static __device__ __forceinline__ int dp4a(uint32_t a, uint32_t b, int c) {
    int r;
    asm("dp4a.s32.s32 %0, %1, %2, %3;" : "=r"(r) : "r"(a), "r"(b), "r"(c));
    return r;
}
static __device__ __forceinline__ void bulk_ld(uint32_t dst, const void* src,
                                               uint32_t bytes, uint32_t mbar) {
    asm volatile("cp.async.bulk.shared::cluster.global.mbarrier::complete_tx::bytes "
                 "[%0], [%1], %2, [%3];"
                 :: "r"(dst), "l"(src), "r"(bytes), "r"(mbar) : "memory");
}
#define MBARRIER_INIT(addr, cnt) \
    asm volatile("mbarrier.init.shared.b64 [%0], %1;" :: "r"((uint32_t)(addr)), "r"((uint32_t)(cnt)) : "memory")
#define MBARRIER_EXPECT_TX(addr, bytes) \
    asm volatile("mbarrier.arrive.expect_tx.shared.b64 _, [%0], %1;" :: "r"((uint32_t)(addr)), "r"((uint32_t)(bytes)) : "memory")
#define MBARRIER_WAIT_PARITY(mbar_addr, parity) do { \
    uint32_t _mbar = (uint32_t)(mbar_addr); \
    uint32_t _par = (uint32_t)(parity); \
    uint32_t _done; \
    asm volatile("{\n\t.reg .pred p;\n\t" \
        "mbarrier.try_wait.parity.acquire.cta.shared::cta.b64 p, [%1], %2;\n\t" \
        "selp.b32 %0, 1, 0, p;\n\t}" : "=r"(_done) : "r"(_mbar), "r"(_par) : "memory"); \
    if (!_done) { \
        asm volatile("{\n\t.reg .pred P1;\n\t" \
            "WAIT_LOOP_%=:\n\t" \
            "mbarrier.try_wait.parity.acquire.cta.shared::cta.b64 P1, [%0], %1, 0x989680;\n\t" \
            "@P1 bra.uni WAIT_DONE_%=;\n\t" \
            "bra.uni WAIT_LOOP_%=;\n\t" \
            "WAIT_DONE_%=:\n\t}" :: "r"(_mbar), "r"(_par) : "memory"); \
    } \
} while (0)

// ---------------- Kernel A: normalize + s8 quantize into [kq][row] panels ---
__global__ void prep_kernel(const float* __restrict__ q, const float* __restrict__ u) {
    int row  = blockIdx.x * (blockDim.x >> 5) + (threadIdx.x >> 5);
    int lane = threadIdx.x & 31;   // lane = kq word index
    int total = NU + BQ + NSPLIT * PADROWS;
    if (row >= total) return;

    if (row >= NU + BQ) {
        // zero a pad column of the last tile of a split (all 32 kq words)
        int pidx = row - (NU + BQ);
        int sp = pidx / PADROWS;
        int r  = (TN - PADROWS) + (pidx % PADROWS);   // user col 40..127
        size_t base = ((size_t)(sp * NTILES + (NTILES - 1))) << 12;
        g_ubsw[base + (size_t)lane * 128 + r] = 0u;
        return;
    }

    const float* src;
    if (row < NU) src = u + (size_t)row * DIM;
    else          src = q + (size_t)(row - NU) * DIM;
    float4 v = *(const float4*)(src + lane * 4);
    float s = v.x * v.x + v.y * v.y + v.z * v.z + v.w * v.w;
    #pragma unroll
    for (int o = 16; o > 0; o >>= 1) s += __shfl_xor_sync(0xffffffffu, s, o);
    float inv = 1.0f / fmaxf(sqrtf(s), 1e-12f);
    float4 o4 = make_float4(v.x * inv, v.y * inv, v.z * inv, v.w * inv);

    int i0 = __float2int_rn(o4.x * 127.0f);
    int i1 = __float2int_rn(o4.y * 127.0f);
    int i2 = __float2int_rn(o4.z * 127.0f);
    int i3 = __float2int_rn(o4.w * 127.0f);
    uint32_t pk = (uint32_t)(i0 & 0xff) | ((uint32_t)(i1 & 0xff) << 8) |
                  ((uint32_t)(i2 & 0xff) << 16) | ((uint32_t)(i3 & 0xff) << 24);

    if (row < NU) {
        *(float4*)(g_ue_n + (size_t)row * DIM + lane * 4) = o4;
        int sp = row / NPS, li = row % NPS;
        int tile = li >> 7, n = li & 127;
        size_t base = ((size_t)(sp * NTILES + tile)) << 12;
        g_ubsw[base + (size_t)lane * 128 + n] = pk;
    } else {
        int r = row - NU;
        *(float4*)(g_q_n + (size_t)r * DIM + lane * 4) = o4;
        int qb = r >> 7, m = r & 127;
        g_qa[((size_t)qb << 12) + (size_t)lane * 128 + m] = pk;
    }
}

// ---------------- Kernel B: dp4a s8 sims + spill/scan top-12 ----------------
// 256 threads (16x16), 8x8 outputs per thread
#define OFF_A    0
#define OFF_B0   16384
#define OFF_B1   32768
#define OFF_SIMS 49152
#define OFF_THR  (OFF_SIMS + 128 * SP_U32 * 4)     // 49152 + 67584 = 116736
#define OFF_TRIG (OFF_THR + 512)                   // 117248
#define OFF_MBAR (OFF_TRIG + 512)                  // 117760
#define SMEM_BYTES (OFF_MBAR + 64 + 1024)          // ~118.8KB

__global__ __launch_bounds__(256) void cand_kernel() {
    extern __shared__ char sraw[];
    uint32_t sb0 = smem_u32(sraw);
    uint32_t ab = (sb0 + 1023) & ~1023u;
    char* base = sraw + (ab - sb0);

    int* simsu = (int*)(base + OFF_SIMS);
    int* thr   = (int*)(base + OFF_THR);
    int* trig  = (int*)(base + OFF_TRIG);
    const uint32_t MB = ab + OFF_MBAR;

    const int t = threadIdx.x;
    const int tx = t & 15, ty = t >> 4;
    const int m0 = ty * 8, n0 = tx * 8;
    const int q0 = blockIdx.x * TM;
    const int sp = blockIdx.y;
    const int u0 = sp * NPS;

    int topv[CAND]; int topi[CAND];
    #pragma unroll
    for (int p = 0; p < CAND; p++) { topv[p] = INT_MIN_V; topi[p] = 0; }

    if (t == 0) { MBARRIER_INIT(MB, 1); MBARRIER_INIT(MB + 8, 1); }
    for (int i = t; i < TM; i += 256) { thr[i] = INT_MIN_V; trig[i] = 0; }

    // load query panel (16KB, plain layout)
    {
        const uint4* src = (const uint4*)(g_qa + ((size_t)blockIdx.x << 12));
        uint4* dst = (uint4*)(base + OFF_A);
        for (int i = t; i < 1024; i += 256) dst[i] = src[i];
    }
    __syncthreads();

    const uint32_t* As = (const uint32_t*)(base + OFF_A);
    const uint32_t* Bp[2] = { (const uint32_t*)(base + OFF_B0),
                              (const uint32_t*)(base + OFF_B1) };
    const uint32_t Bs_[2] = { ab + OFF_B0, ab + OFF_B1 };
    const char* tb = (const char*)g_ubsw + ((size_t)sp * NTILES << 14);

    if (t == 0) {
        MBARRIER_EXPECT_TX(MB,     16384u); bulk_ld(Bs_[0], tb,         16384u, MB);
        MBARRIER_EXPECT_TX(MB + 8, 16384u); bulk_ld(Bs_[1], tb + 16384, 16384u, MB + 8);
    }

    int ph[2] = {0, 0};
    for (int i = 0; i < NTILES; i++) {
        const int s = i & 1;
        const uint32_t* Bs = Bp[s];
        MBARRIER_WAIT_PARITY(MB + s * 8, ph[s]); ph[s] ^= 1;

        // ---- dp4a GEMM: 8x8 outputs per thread, k = 32 u32 words ----
        int acc[8][8];
        #pragma unroll
        for (int mi = 0; mi < 8; mi++)
            #pragma unroll
            for (int ni = 0; ni < 8; ni++) acc[mi][ni] = 0;

        #pragma unroll 4
        for (int kq = 0; kq < 32; kq++) {
            uint4 a0 = *(const uint4*)(As + kq * 128 + m0);
            uint4 a1 = *(const uint4*)(As + kq * 128 + m0 + 4);
            uint4 b0 = *(const uint4*)(Bs + kq * 128 + n0);
            uint4 b1 = *(const uint4*)(Bs + kq * 128 + n0 + 4);
            uint32_t a[8] = {a0.x, a0.y, a0.z, a0.w, a1.x, a1.y, a1.z, a1.w};
            uint32_t b[8] = {b0.x, b0.y, b0.z, b0.w, b1.x, b1.y, b1.z, b1.w};
            #pragma unroll
            for (int mi = 0; mi < 8; mi++)
                #pragma unroll
                for (int ni = 0; ni < 8; ni++)
                    acc[mi][ni] = dp4a(a[mi], b[ni], acc[mi][ni]);
        }

        // ---- per-row max over this thread's 8 cols + threshold trig ----
        #pragma unroll
        for (int mi = 0; mi < 8; mi++) {
            int mx = acc[mi][0];
            #pragma unroll
            for (int ni = 1; ni < 8; ni++) mx = max(mx, acc[mi][ni]);
            int row = m0 + mi;
            if (mx > thr[row]) trig[row] = 1;   // benign race
        }
        __syncthreads();   // trig visible; B[s] fully consumed

        // ---- spill triggered rows (each thread: its 8-col slice) ----
        #pragma unroll
        for (int mi = 0; mi < 8; mi++) {
            int row = m0 + mi;
            if (trig[row]) {
                *(int4*)&simsu[row * SP_U32 + n0] =
                    make_int4(acc[mi][0], acc[mi][1], acc[mi][2], acc[mi][3]);
                *(int4*)&simsu[row * SP_U32 + n0 + 4] =
                    make_int4(acc[mi][4], acc[mi][5], acc[mi][6], acc[mi][7]);
            }
        }
        if (t == 0 && i + 2 < NTILES) {
            MBARRIER_EXPECT_TX(MB + s * 8, 16384u);
            bulk_ld(Bs_[s], tb + ((size_t)(i + 2) << 14), 16384u, MB + s * 8);
        }
        __syncthreads();   // sims visible

        // ---- owner threads (t<128) scan triggered rows ----
        if (t < TM && trig[t]) {
            int nvalid = min(TN, NPS - i * TN);
            int cbase = u0 + i * TN;
            const int* srow = simsu + t * SP_U32;
            for (int c = 0; c < nvalid; c++) {
                int v = srow[c];
                int idx = cbase + c;
                if (v > topv[CAND - 1] ||
                    (v == topv[CAND - 1] && idx < topi[CAND - 1])) {
                    int vv = v, ii = idx;
                    #pragma unroll
                    for (int p = 0; p < CAND; p++) {
                        bool better = (vv > topv[p]) || (vv == topv[p] && ii < topi[p]);
                        if (better) {
                            int tv = topv[p]; topv[p] = vv; vv = tv;
                            int ti = topi[p]; topi[p] = ii; ii = ti;
                        }
                    }
                }
            }
            thr[t] = topv[CAND - 1];
            trig[t] = 0;
        }
        __syncthreads();
    }

    if (t < TM) {
        size_t b = (size_t)(q0 + t) * NCAND + sp * CAND;
        #pragma unroll
        for (int e = 0; e < CAND; e++) g_ci[b + e] = topi[e];
    }
}

// ---------------- Kernel C: exact rescore + select + gather -----------------
__global__ void finalize_kernel(float* __restrict__ out) {
    __shared__ float cv[NCAND];
    __shared__ int   ci[NCAND];
    __shared__ int   sel[TOPK];
    __shared__ float selv[TOPK];

    const int q = blockIdx.x;
    const int t = threadIdx.x;
    const int w = t >> 5, lane = t & 31;

    if (t < NCAND) ci[t] = g_ci[(size_t)q * NCAND + t];
    __syncthreads();

    float4 qv = *(const float4*)(g_q_n + (size_t)q * DIM + lane * 4);
    #pragma unroll 1
    for (int cc = 0; cc < CAND; cc++) {
        int idx = ci[w * CAND + cc];
        float4 uv = *(const float4*)(g_ue_n + (size_t)idx * DIM + lane * 4);
        float s = qv.x * uv.x;
        s = fmaf(qv.y, uv.y, s);
        s = fmaf(qv.z, uv.z, s);
        s = fmaf(qv.w, uv.w, s);
        #pragma unroll
        for (int o = 16; o > 0; o >>= 1) s += __shfl_xor_sync(0xffffffffu, s, o);
        if (lane == 0) cv[w * CAND + cc] = s;
    }
    __syncthreads();

    if (t == 0) {
        float bv[K1]; int bi[K1]; int cnt = 0;
        for (int i = 0; i < NCAND; i++) {
            float v = cv[i]; int id = ci[i];
            bool better = (cnt < K1) || (v > bv[K1 - 1]) || (v == bv[K1 - 1] && id < bi[K1 - 1]);
            if (!better) continue;
            int j = (cnt < K1) ? cnt : K1 - 1;
            while (j > 0 && (v > bv[j - 1] || (v == bv[j - 1] && id < bi[j - 1]))) {
                bv[j] = bv[j - 1]; bi[j] = bi[j - 1]; j--;
            }
            bv[j] = v; bi[j] = id;
            if (cnt < K1) cnt++;
        }
        int order[K1]; int nv = 0;
        for (int i = 0; i < K1; i++) if (bv[i] < 0.9999f) order[nv++] = i;
        int oi = nv;
        for (int i = 0; i < K1; i++) if (!(bv[i] < 0.9999f)) order[oi++] = i;
        for (int j = 0; j < TOPK; j++) {
            int pos = (nv > 0) ? order[min(j, nv - 1)] : j;
            sel[j] = bi[pos]; selv[j] = bv[pos];
        }
    }
    __syncthreads();

    float* oute = out;                              // [BQ, TOPK, DIM]
    float* outs = out + (size_t)BQ * TOPK * DIM;    // [BQ, TOPK]
    #pragma unroll
    for (int j = 0; j < TOPK; j++)
        oute[((size_t)q * TOPK + j) * DIM + t] = g_ue_n[(size_t)sel[j] * DIM + t];
    if (t < TOPK) outs[(size_t)q * TOPK + t] = selv[t];
}

// ---------------- launch ----------------------------------------------------
extern "C" void kernel_launch(void* const* d_in, const int* in_sizes, int n_in,
                              void* d_out, int out_size) {
    const float* q = (const float*)d_in[0];
    const float* u = (const float*)d_in[1];
    if (n_in >= 2 && in_sizes[0] != BQ * DIM) { const float* tmp = q; q = u; u = tmp; }
    float* out = (float*)d_out;

    int rows = NU + BQ + NSPLIT * PADROWS;
    prep_kernel<<<(rows + 7) / 8, 256>>>(q, u);

    cudaFuncSetAttribute(cand_kernel, cudaFuncAttributeMaxDynamicSharedMemorySize, SMEM_BYTES);
    cand_kernel<<<dim3(QB, NSPLIT), 256, SMEM_BYTES>>>();

    finalize_kernel<<<BQ, DIM>>>(out);
}

// round 11
// speedup vs baseline: 1.0500x; 1.0500x over previous
#include <cuda_runtime.h>
#include <cuda_fp16.h>
#include <math.h>
#include <cstdint>

// ---------------- problem constants ----------------
#define BQ   4096
#define NU   100000
#define DIM  128
#define TOPK 5
#define K1   6
#define NSPLIT 4
#define NPS   25000
#define TM 128
#define TN 128
#define QB (BQ / TM)                   // 32
#define NTILES ((NPS + TN - 1) / TN)   // 196
#define PADROWS (NTILES * TN - NPS)    // 88
#define CAND 12
#define NCAND (NSPLIT * CAND)          // 48
#define SPITCH 132                     // sims pitch (floats), 16B-aligned rows
#define NEG_INF (-3.402823466e38f)
#define TILE_BYTES 24576               // 16KB f16 half + 8KB s8 panel
#define DSCALE (1.0f / 16129.0f)       // 1/(127*127)

// ---------------- device scratch -------------------------------------------
__device__ float    g_ue_n[(size_t)NU * DIM];
__device__ float    g_q_n[(size_t)BQ * DIM];
// per (split,tile): [f16 half-tile 16384B][s8 panel 8192B]
__device__ uint32_t g_ut[(size_t)NSPLIT * NTILES * (TILE_BYTES / 4)];
__device__ __half   g_qh[(size_t)BQ * DIM];       // f16 queries row-major
__device__ uint32_t g_qa[(size_t)QB * 4096];      // s8 query panels [32kq][128m]
__device__ int      g_ci[(size_t)BQ * NCAND];

// ---------------- helpers ---------------------------------------------------
static __device__ __forceinline__ uint32_t smem_u32(const void* p) {
    uint32_t a;
    asm("{ .reg .u64 t; cvta.to.shared.u64 t, %1; cvt.u32.u64 %0, t; }" : "=r"(a) : "l"(p));
    return a;
}
static __device__ __forceinline__ int dp4a(uint32_t a, uint32_t b, int c) {
    int r;
    asm("dp4a.s32.s32 %0, %1, %2, %3;" : "=r"(r) : "r"(a), "r"(b), "r"(c));
    return r;
}
static __device__ __forceinline__ void ldsm_x4(uint32_t addr, uint32_t r[4]) {
    asm volatile("ldmatrix.sync.aligned.m8n8.x4.shared.b16 {%0,%1,%2,%3}, [%4];"
                 : "=r"(r[0]), "=r"(r[1]), "=r"(r[2]), "=r"(r[3]) : "r"(addr));
}
static __device__ __forceinline__ void mma_f16(uint32_t c[2], const uint32_t a[4],
                                               uint32_t b0, uint32_t b1) {
    asm volatile("mma.sync.aligned.m16n8k16.row.col.f16.f16.f16.f16 "
                 "{%0,%1}, {%2,%3,%4,%5}, {%6,%7}, {%0,%1};"
                 : "+r"(c[0]), "+r"(c[1])
                 : "r"(a[0]), "r"(a[1]), "r"(a[2]), "r"(a[3]), "r"(b0), "r"(b1));
}
static __device__ __forceinline__ void bulk_ld(uint32_t dst, const void* src,
                                               uint32_t bytes, uint32_t mbar) {
    asm volatile("cp.async.bulk.shared::cluster.global.mbarrier::complete_tx::bytes "
                 "[%0], [%1], %2, [%3];"
                 :: "r"(dst), "l"(src), "r"(bytes), "r"(mbar) : "memory");
}
#define MBARRIER_INIT(addr, cnt) \
    asm volatile("mbarrier.init.shared.b64 [%0], %1;" :: "r"((uint32_t)(addr)), "r"((uint32_t)(cnt)) : "memory")
#define MBARRIER_EXPECT_TX(addr, bytes) \
    asm volatile("mbarrier.arrive.expect_tx.shared.b64 _, [%0], %1;" :: "r"((uint32_t)(addr)), "r"((uint32_t)(bytes)) : "memory")
#define MBARRIER_WAIT_PARITY(mbar_addr, parity) do { \
    uint32_t _mbar = (uint32_t)(mbar_addr); \
    uint32_t _par = (uint32_t)(parity); \
    uint32_t _done; \
    asm volatile("{\n\t.reg .pred p;\n\t" \
        "mbarrier.try_wait.parity.acquire.cta.shared::cta.b64 p, [%1], %2;\n\t" \
        "selp.b32 %0, 1, 0, p;\n\t}" : "=r"(_done) : "r"(_mbar), "r"(_par) : "memory"); \
    if (!_done) { \
        asm volatile("{\n\t.reg .pred P1;\n\t" \
            "WAIT_LOOP_%=:\n\t" \
            "mbarrier.try_wait.parity.acquire.cta.shared::cta.b64 P1, [%0], %1, 0x989680;\n\t" \
            "@P1 bra.uni WAIT_DONE_%=;\n\t" \
            "bra.uni WAIT_LOOP_%=;\n\t" \
            "WAIT_DONE_%=:\n\t}" :: "r"(_mbar), "r"(_par) : "memory"); \
    } \
} while (0)

// swizzled byte offset inside a [rows x 256B] f16 tile (16B chunks, XOR by row)
static __device__ __forceinline__ uint32_t tile_off(int r, int chunk) {
    return (uint32_t)(r * 256 + ((chunk ^ (r & 7)) << 4));
}

// ---------------- Kernel A: normalize + dual-format quantize ----------------
__global__ void prep_kernel(const float* __restrict__ q, const float* __restrict__ u) {
    int row  = blockIdx.x * (blockDim.x >> 5) + (threadIdx.x >> 5);
    int lane = threadIdx.x & 31;
    int total = NU + BQ + NSPLIT * PADROWS;
    if (row >= total) return;

    if (row >= NU + BQ) {
        // pad slot: user col n in [40,128) of the last tile of split sp
        int pidx = row - (NU + BQ);
        int sp = pidx / PADROWS;
        int n  = (TN - PADROWS) + (pidx % PADROWS);
        size_t tbase = (size_t)(sp * NTILES + (NTILES - 1)) * (TILE_BYTES / 4);
        if (n < 64) {       // zero f16 row n: 64 u32, 2 per lane
            uint32_t off = tile_off(n, lane >> 1) >> 2;
            g_ut[tbase + off + (lane & 1) * 2]     = 0u;
            g_ut[tbase + off + (lane & 1) * 2 + 1] = 0u;
        } else {            // zero s8 panel col: word kq*64 + (n-64), kq = lane
            g_ut[tbase + 4096 + (size_t)lane * 64 + (n - 64)] = 0u;
        }
        return;
    }

    const float* src;
    if (row < NU) src = u + (size_t)row * DIM;
    else          src = q + (size_t)(row - NU) * DIM;
    float4 v = *(const float4*)(src + lane * 4);
    float s = v.x * v.x + v.y * v.y + v.z * v.z + v.w * v.w;
    #pragma unroll
    for (int o = 16; o > 0; o >>= 1) s += __shfl_xor_sync(0xffffffffu, s, o);
    float inv = 1.0f / fmaxf(sqrtf(s), 1e-12f);
    float4 o4 = make_float4(v.x * inv, v.y * inv, v.z * inv, v.w * inv);

    // f16 pack
    __half2 h0 = __floats2half2_rn(o4.x, o4.y);
    __half2 h1 = __floats2half2_rn(o4.z, o4.w);
    uint32_t f0 = *(uint32_t*)&h0, f1 = *(uint32_t*)&h1;
    // s8 pack
    int i0 = __float2int_rn(o4.x * 127.0f);
    int i1 = __float2int_rn(o4.y * 127.0f);
    int i2 = __float2int_rn(o4.z * 127.0f);
    int i3 = __float2int_rn(o4.w * 127.0f);
    uint32_t pk = (uint32_t)(i0 & 0xff) | ((uint32_t)(i1 & 0xff) << 8) |
                  ((uint32_t)(i2 & 0xff) << 16) | ((uint32_t)(i3 & 0xff) << 24);

    if (row < NU) {
        *(float4*)(g_ue_n + (size_t)row * DIM + lane * 4) = o4;
        int sp = row / NPS, li = row % NPS;
        int tile = li >> 7, n = li & 127;
        size_t tbase = (size_t)(sp * NTILES + tile) * (TILE_BYTES / 4);
        if (n < 64) {
            uint32_t off = tile_off(n, lane >> 1) >> 2;
            g_ut[tbase + off + (lane & 1) * 2]     = f0;
            g_ut[tbase + off + (lane & 1) * 2 + 1] = f1;
        } else {
            g_ut[tbase + 4096 + (size_t)lane * 64 + (n - 64)] = pk;
        }
    } else {
        int r = row - NU;
        *(float4*)(g_q_n + (size_t)r * DIM + lane * 4) = o4;
        uint2 ph = make_uint2(f0, f1);
        *(uint2*)(g_qh + (size_t)r * DIM + lane * 4) = ph;
        int qb = r >> 7, m = r & 127;
        g_qa[((size_t)qb << 12) + (size_t)lane * 128 + m] = pk;
    }
}

// ---------------- Kernel B: hybrid f16-mma + dp4a sims, top-12 --------------
// 512 threads: warps 0-7 = f16 mma on cols [0,64); warps 8-15 = dp4a on [64,128)
#define OFF_AH   0
#define OFF_AD   32768
#define OFF_B0   49152
#define OFF_B1   73728
#define OFF_SIMS 98304
#define OFF_THR  (OFF_SIMS + 128 * SPITCH * 4)     // 165888
#define OFF_TRIG (OFF_THR + 512)                   // 166400
#define OFF_MBAR (OFF_TRIG + 512)                  // 166912
#define SMEM_BYTES (OFF_MBAR + 64 + 1024)

__global__ __launch_bounds__(512) void cand_kernel() {
    extern __shared__ char sraw[];
    uint32_t sb0 = smem_u32(sraw);
    uint32_t ab = (sb0 + 1023) & ~1023u;
    char* base = sraw + (ab - sb0);

    float* sims = (float*)(base + OFF_SIMS);
    float* thr  = (float*)(base + OFF_THR);
    int*   trig = (int*)(base + OFF_TRIG);
    const uint32_t MB = ab + OFF_MBAR;

    const int t = threadIdx.x;
    const int w = t >> 5, lane = t & 31;
    const int q0 = blockIdx.x * TM;
    const int sp = blockIdx.y;
    const int u0 = sp * NPS;

    float topv[CAND]; int topi[CAND];
    #pragma unroll
    for (int p = 0; p < CAND; p++) { topv[p] = NEG_INF; topi[p] = 0; }

    if (t == 0) { MBARRIER_INIT(MB, 1); MBARRIER_INIT(MB + 8, 1); }
    for (int i = t; i < TM; i += 512) { thr[i] = NEG_INF; trig[i] = 0; }

    // build query f16 swizzled tile + copy query s8 panel
    {
        const uint4* src = (const uint4*)(g_qh + (size_t)q0 * DIM);
        for (int i = t; i < TM * 16; i += 512) {
            int r = i >> 4, c = i & 15;
            *(uint4*)(base + OFF_AH + tile_off(r, c)) = src[i];
        }
        const uint4* sqa = (const uint4*)(g_qa + ((size_t)blockIdx.x << 12));
        uint4* dqa = (uint4*)(base + OFF_AD);
        for (int i = t; i < 1024; i += 512) dqa[i] = sqa[i];
    }
    __syncthreads();

    const uint32_t A_s = ab + OFF_AH;
    const uint32_t* Ad = (const uint32_t*)(base + OFF_AD);
    const uint32_t Bb_[2] = { ab + OFF_B0, ab + OFF_B1 };
    const char* tb = (const char*)g_ut + (size_t)sp * NTILES * TILE_BYTES;

    if (t == 0) {
        MBARRIER_EXPECT_TX(MB,     TILE_BYTES); bulk_ld(Bb_[0], tb,              TILE_BYTES, MB);
        MBARRIER_EXPECT_TX(MB + 8, TILE_BYTES); bulk_ld(Bb_[1], tb + TILE_BYTES, TILE_BYTES, MB + 8);
    }

    // H-warp addressing (warps 0-7: 4m x 2n grid, warp tile 32x32)
    const int m0H = (w >> 1) * 32;
    const int n0H = (w & 1) * 32;
    const int a_row0 = m0H + (lane & 15);
    const int b_row0 = n0H + (lane & 7) + ((lane >> 4) << 3);
    const int a_chsel = (lane >> 4);
    const int b_chsel = ((lane >> 3) & 1);
    // D-thread addressing (warps 8-15: 256 threads, 4 rows x 8 cols each)
    const int td = t - 256;
    const int m0d = (td >> 3) * 4;
    const int n0d = (td & 7) * 8;

    int ph[2] = {0, 0};
    for (int i = 0; i < NTILES; i++) {
        const int s = i & 1;
        const uint32_t Bb = Bb_[s];
        MBARRIER_WAIT_PARITY(MB + s * 8, ph[s]); ph[s] ^= 1;

        if (w < 8) {
            // ================= H path: f16 mma, cols [0,64) =================
            uint32_t acc[2][4][2];
            #pragma unroll
            for (int mi = 0; mi < 2; mi++)
                #pragma unroll
                for (int nf = 0; nf < 4; nf++) { acc[mi][nf][0] = 0u; acc[mi][nf][1] = 0u; }

            #pragma unroll
            for (int k = 0; k < 8; k++) {
                uint32_t af[2][4], bf[2][4];
                ldsm_x4(A_s + tile_off(a_row0,      2 * k + a_chsel), af[0]);
                ldsm_x4(A_s + tile_off(a_row0 + 16, 2 * k + a_chsel), af[1]);
                ldsm_x4(Bb  + tile_off(b_row0,      2 * k + b_chsel), bf[0]);
                ldsm_x4(Bb  + tile_off(b_row0 + 16, 2 * k + b_chsel), bf[1]);
                #pragma unroll
                for (int g = 0; g < 2; g++) {
                    mma_f16(acc[0][g * 2 + 0], af[0], bf[g][0], bf[g][1]);
                    mma_f16(acc[1][g * 2 + 0], af[1], bf[g][0], bf[g][1]);
                    mma_f16(acc[0][g * 2 + 1], af[0], bf[g][2], bf[g][3]);
                    mma_f16(acc[1][g * 2 + 1], af[1], bf[g][2], bf[g][3]);
                }
            }
            // row-max + trig
            #pragma unroll
            for (int mi = 0; mi < 2; mi++)
                #pragma unroll
                for (int h = 0; h < 2; h++) {
                    __half2 m2 = *(__half2*)&acc[mi][0][h];
                    #pragma unroll
                    for (int nf = 1; nf < 4; nf++)
                        m2 = __hmax2(m2, *(__half2*)&acc[mi][nf][h]);
                    float mx = fmaxf(__low2float(m2), __high2float(m2));
                    mx = fmaxf(mx, __shfl_xor_sync(0xffffffffu, mx, 1));
                    mx = fmaxf(mx, __shfl_xor_sync(0xffffffffu, mx, 2));
                    int row = m0H + mi * 16 + (lane >> 2) + h * 8;
                    if ((lane & 3) == 0 && mx > thr[row]) trig[row] = 1;
                }
            __syncthreads();   // (1) trig visible, B[s] consumed by H

            // spill triggered rows (convert f16 -> float)
            #pragma unroll
            for (int mi = 0; mi < 2; mi++) {
                int r0 = m0H + mi * 16 + (lane >> 2);
                #pragma unroll
                for (int h = 0; h < 2; h++) {
                    int row = r0 + h * 8;
                    if (trig[row]) {
                        #pragma unroll
                        for (int nf = 0; nf < 4; nf++) {
                            __half2 hv = *(__half2*)&acc[mi][nf][h];
                            int c0 = n0H + nf * 8 + (lane & 3) * 2;
                            *(float2*)&sims[row * SPITCH + c0] =
                                make_float2(__low2float(hv), __high2float(hv));
                        }
                    }
                }
            }
        } else {
            // ================= D path: dp4a, cols [64,128) ===================
            const uint32_t* Bd = (const uint32_t*)(base + (Bb - ab) + 16384);
            int accd[4][8];
            #pragma unroll
            for (int mi = 0; mi < 4; mi++)
                #pragma unroll
                for (int ni = 0; ni < 8; ni++) accd[mi][ni] = 0;

            #pragma unroll 4
            for (int kq = 0; kq < 32; kq++) {
                uint4 a4 = *(const uint4*)(Ad + kq * 128 + m0d);
                uint4 b0 = *(const uint4*)(Bd + kq * 64 + n0d);
                uint4 b1 = *(const uint4*)(Bd + kq * 64 + n0d + 4);
                uint32_t a[4] = {a4.x, a4.y, a4.z, a4.w};
                uint32_t b[8] = {b0.x, b0.y, b0.z, b0.w, b1.x, b1.y, b1.z, b1.w};
                #pragma unroll
                for (int mi = 0; mi < 4; mi++)
                    #pragma unroll
                    for (int ni = 0; ni < 8; ni++)
                        accd[mi][ni] = dp4a(a[mi], b[ni], accd[mi][ni]);
            }
            // convert to float scale, row-max + trig
            float fv[4][8];
            #pragma unroll
            for (int mi = 0; mi < 4; mi++) {
                float mx = NEG_INF;
                #pragma unroll
                for (int ni = 0; ni < 8; ni++) {
                    fv[mi][ni] = (float)accd[mi][ni] * DSCALE;
                    mx = fmaxf(mx, fv[mi][ni]);
                }
                int row = m0d + mi;
                if (mx > thr[row]) trig[row] = 1;
            }
            __syncthreads();   // (1)

            #pragma unroll
            for (int mi = 0; mi < 4; mi++) {
                int row = m0d + mi;
                if (trig[row]) {
                    *(float4*)&sims[row * SPITCH + 64 + n0d] =
                        make_float4(fv[mi][0], fv[mi][1], fv[mi][2], fv[mi][3]);
                    *(float4*)&sims[row * SPITCH + 64 + n0d + 4] =
                        make_float4(fv[mi][4], fv[mi][5], fv[mi][6], fv[mi][7]);
                }
            }
        }

        if (t == 0 && i + 2 < NTILES) {
            MBARRIER_EXPECT_TX(MB + s * 8, TILE_BYTES);
            bulk_ld(Bb, tb + (size_t)(i + 2) * TILE_BYTES, TILE_BYTES, MB + s * 8);
        }
        __syncthreads();   // (2) sims visible

        // owner threads (t<128) scan triggered rows
        if (t < TM && trig[t]) {
            int nvalid = min(TN, NPS - i * TN);
            int cbase = u0 + i * TN;
            const float* srow = sims + t * SPITCH;
            for (int c = 0; c < nvalid; c++) {
                float v = srow[c];
                int idx = cbase + c;
                if (v > topv[CAND - 1] ||
                    (v == topv[CAND - 1] && idx < topi[CAND - 1])) {
                    float vv = v; int ii = idx;
                    #pragma unroll
                    for (int p = 0; p < CAND; p++) {
                        bool better = (vv > topv[p]) || (vv == topv[p] && ii < topi[p]);
                        if (better) {
                            float tv = topv[p]; topv[p] = vv; vv = tv;
                            int   ti = topi[p]; topi[p] = ii; ii = ti;
                        }
                    }
                }
            }
            thr[t] = topv[CAND - 1];
            trig[t] = 0;
        }
        __syncthreads();   // (3)
    }

    if (t < TM) {
        size_t b = (size_t)(q0 + t) * NCAND + sp * CAND;
        #pragma unroll
        for (int e = 0; e < CAND; e++) g_ci[b + e] = topi[e];
    }
}

// ---------------- Kernel C: exact rescore + select + gather -----------------
__global__ void finalize_kernel(float* __restrict__ out) {
    __shared__ float cv[NCAND];
    __shared__ int   ci[NCAND];
    __shared__ int   sel[TOPK];
    __shared__ float selv[TOPK];

    const int q = blockIdx.x;
    const int t = threadIdx.x;
    const int w = t >> 5, lane = t & 31;

    if (t < NCAND) ci[t] = g_ci[(size_t)q * NCAND + t];
    __syncthreads();

    float4 qv = *(const float4*)(g_q_n + (size_t)q * DIM + lane * 4);
    #pragma unroll 1
    for (int cc = 0; cc < CAND; cc++) {
        int idx = ci[w * CAND + cc];
        float4 uv = *(const float4*)(g_ue_n + (size_t)idx * DIM + lane * 4);
        float s = qv.x * uv.x;
        s = fmaf(qv.y, uv.y, s);
        s = fmaf(qv.z, uv.z, s);
        s = fmaf(qv.w, uv.w, s);
        #pragma unroll
        for (int o = 16; o > 0; o >>= 1) s += __shfl_xor_sync(0xffffffffu, s, o);
        if (lane == 0) cv[w * CAND + cc] = s;
    }
    __syncthreads();

    if (t == 0) {
        float bv[K1]; int bi[K1]; int cnt = 0;
        for (int i = 0; i < NCAND; i++) {
            float v = cv[i]; int id = ci[i];
            bool better = (cnt < K1) || (v > bv[K1 - 1]) || (v == bv[K1 - 1] && id < bi[K1 - 1]);
            if (!better) continue;
            int j = (cnt < K1) ? cnt : K1 - 1;
            while (j > 0 && (v > bv[j - 1] || (v == bv[j - 1] && id < bi[j - 1]))) {
                bv[j] = bv[j - 1]; bi[j] = bi[j - 1]; j--;
            }
            bv[j] = v; bi[j] = id;
            if (cnt < K1) cnt++;
        }
        int order[K1]; int nv = 0;
        for (int i = 0; i < K1; i++) if (bv[i] < 0.9999f) order[nv++] = i;
        int oi = nv;
        for (int i = 0; i < K1; i++) if (!(bv[i] < 0.9999f)) order[oi++] = i;
        for (int j = 0; j < TOPK; j++) {
            int pos = (nv > 0) ? order[min(j, nv - 1)] : j;
            sel[j] = bi[pos]; selv[j] = bv[pos];
        }
    }
    __syncthreads();

    float* oute = out;                              // [BQ, TOPK, DIM]
    float* outs = out + (size_t)BQ * TOPK * DIM;    // [BQ, TOPK]
    #pragma unroll
    for (int j = 0; j < TOPK; j++)
        oute[((size_t)q * TOPK + j) * DIM + t] = g_ue_n[(size_t)sel[j] * DIM + t];
    if (t < TOPK) outs[(size_t)q * TOPK + t] = selv[t];
}

// ---------------- launch ----------------------------------------------------
extern "C" void kernel_launch(void* const* d_in, const int* in_sizes, int n_in,
                              void* d_out, int out_size) {
    const float* q = (const float*)d_in[0];
    const float* u = (const float*)d_in[1];
    if (n_in >= 2 && in_sizes[0] != BQ * DIM) { const float* tmp = q; q = u; u = tmp; }
    float* out = (float*)d_out;

    int rows = NU + BQ + NSPLIT * PADROWS;
    prep_kernel<<<(rows + 7) / 8, 256>>>(q, u);

    cudaFuncSetAttribute(cand_kernel, cudaFuncAttributeMaxDynamicSharedMemorySize, SMEM_BYTES);
    cand_kernel<<<dim3(QB, NSPLIT), 512, SMEM_BYTES>>>();

    finalize_kernel<<<BQ, DIM>>>(out);
}

// round 12
// speedup vs baseline: 2.2752x; 2.1669x over previous
#include <cuda_runtime.h>
#include <cuda_fp16.h>
#include <math.h>
#include <cstdint>

// ---------------- problem constants ----------------
#define BQ   4096
#define NU   100000
#define DIM  128
#define TOPK 5
#define K1   6
#define TM   256                       // queries per CTA
#define TN   128                       // users per tile
#define QB   (BQ / TM)                 // 16
#define NCHUNK 9                       // user-range chunks
#define NT_FLAT 782                    // ceil(100000/128); last tile: 32 valid + 96 pad
#define PADROWS 96
#define CAND 8
#define NCAND (NCHUNK * CAND)          // 72
#define SP_U32 65                      // half2-spill pitch in u32
#define NEG_INF (-3.402823466e38f)

// ---------------- device scratch -------------------------------------------
__device__ float    g_ue_n[(size_t)NU * DIM];
__device__ float    g_q_n[(size_t)BQ * DIM];
__device__ uint32_t g_ubsw[(size_t)NT_FLAT * 8192];   // flat pre-swizzled f16 tiles (32KB each)
__device__ __half   g_qh[(size_t)BQ * DIM];
__device__ int      g_ci[(size_t)BQ * NCAND];

// ---------------- helpers ---------------------------------------------------
static __device__ __forceinline__ uint32_t smem_u32(const void* p) {
    uint32_t a;
    asm("{ .reg .u64 t; cvta.to.shared.u64 t, %1; cvt.u32.u64 %0, t; }" : "=r"(a) : "l"(p));
    return a;
}
static __device__ __forceinline__ void ldsm_x4(uint32_t addr, uint32_t r[4]) {
    asm volatile("ldmatrix.sync.aligned.m8n8.x4.shared.b16 {%0,%1,%2,%3}, [%4];"
                 : "=r"(r[0]), "=r"(r[1]), "=r"(r[2]), "=r"(r[3]) : "r"(addr));
}
static __device__ __forceinline__ void mma_f16(uint32_t c[2], const uint32_t a[4],
                                               uint32_t b0, uint32_t b1) {
    asm volatile("mma.sync.aligned.m16n8k16.row.col.f16.f16.f16.f16 "
                 "{%0,%1}, {%2,%3,%4,%5}, {%6,%7}, {%0,%1};"
                 : "+r"(c[0]), "+r"(c[1])
                 : "r"(a[0]), "r"(a[1]), "r"(a[2]), "r"(a[3]), "r"(b0), "r"(b1));
}
static __device__ __forceinline__ void bulk_ld(uint32_t dst, const void* src,
                                               uint32_t bytes, uint32_t mbar) {
    asm volatile("cp.async.bulk.shared::cluster.global.mbarrier::complete_tx::bytes "
                 "[%0], [%1], %2, [%3];"
                 :: "r"(dst), "l"(src), "r"(bytes), "r"(mbar) : "memory");
}
#define MBARRIER_INIT(addr, cnt) \
    asm volatile("mbarrier.init.shared.b64 [%0], %1;" :: "r"((uint32_t)(addr)), "r"((uint32_t)(cnt)) : "memory")
#define MBARRIER_EXPECT_TX(addr, bytes) \
    asm volatile("mbarrier.arrive.expect_tx.shared.b64 _, [%0], %1;" :: "r"((uint32_t)(addr)), "r"((uint32_t)(bytes)) : "memory")
#define MBARRIER_WAIT_PARITY(mbar_addr, parity) do { \
    uint32_t _mbar = (uint32_t)(mbar_addr); \
    uint32_t _par = (uint32_t)(parity); \
    uint32_t _done; \
    asm volatile("{\n\t.reg .pred p;\n\t" \
        "mbarrier.try_wait.parity.acquire.cta.shared::cta.b64 p, [%1], %2;\n\t" \
        "selp.b32 %0, 1, 0, p;\n\t}" : "=r"(_done) : "r"(_mbar), "r"(_par) : "memory"); \
    if (!_done) { \
        asm volatile("{\n\t.reg .pred P1;\n\t" \
            "WAIT_LOOP_%=:\n\t" \
            "mbarrier.try_wait.parity.acquire.cta.shared::cta.b64 P1, [%0], %1, 0x989680;\n\t" \
            "@P1 bra.uni WAIT_DONE_%=;\n\t" \
            "bra.uni WAIT_LOOP_%=;\n\t" \
            "WAIT_DONE_%=:\n\t}" :: "r"(_mbar), "r"(_par) : "memory"); \
    } \
} while (0)

// swizzled byte offset inside a [rows x 256B] f16 tile (16B chunks, XOR by row)
static __device__ __forceinline__ uint32_t tile_off(int r, int chunk) {
    return (uint32_t)(r * 256 + ((chunk ^ (r & 7)) << 4));
}

// ---------------- Kernel A: normalize + f16 convert into flat tiles ---------
__global__ void prep_kernel(const float* __restrict__ q, const float* __restrict__ u) {
    int row  = blockIdx.x * (blockDim.x >> 5) + (threadIdx.x >> 5);
    int lane = threadIdx.x & 31;
    int total = NU + BQ + PADROWS;
    if (row >= total) return;

    if (row >= NU + BQ) {
        // zero pad row of last tile (rows 32..127 of tile 781)
        int r = 32 + (row - (NU + BQ));
        size_t tbase = (size_t)(NT_FLAT - 1) << 13;
        uint32_t off = tile_off(r, lane >> 1) >> 2;
        g_ubsw[tbase + off + (lane & 1) * 2]     = 0u;
        g_ubsw[tbase + off + (lane & 1) * 2 + 1] = 0u;
        return;
    }

    const float* src;
    if (row < NU) src = u + (size_t)row * DIM;
    else          src = q + (size_t)(row - NU) * DIM;
    float4 v = *(const float4*)(src + lane * 4);
    float s = v.x * v.x + v.y * v.y + v.z * v.z + v.w * v.w;
    #pragma unroll
    for (int o = 16; o > 0; o >>= 1) s += __shfl_xor_sync(0xffffffffu, s, o);
    float inv = 1.0f / fmaxf(sqrtf(s), 1e-12f);
    float4 o4 = make_float4(v.x * inv, v.y * inv, v.z * inv, v.w * inv);

    __half2 h0 = __floats2half2_rn(o4.x, o4.y);
    __half2 h1 = __floats2half2_rn(o4.z, o4.w);
    uint32_t f0 = *(uint32_t*)&h0, f1 = *(uint32_t*)&h1;

    if (row < NU) {
        *(float4*)(g_ue_n + (size_t)row * DIM + lane * 4) = o4;
        int tile = row >> 7, n = row & 127;
        size_t tbase = (size_t)tile << 13;           // 8192 u32 per tile
        uint32_t off = tile_off(n, lane >> 1) >> 2;
        g_ubsw[tbase + off + (lane & 1) * 2]     = f0;
        g_ubsw[tbase + off + (lane & 1) * 2 + 1] = f1;
    } else {
        int r = row - NU;
        *(float4*)(g_q_n + (size_t)r * DIM + lane * 4) = o4;
        uint2 pk = make_uint2(f0, f1);
        *(uint2*)(g_qh + (size_t)r * DIM + lane * 4) = pk;
    }
}

// ---------------- Kernel B: f16 HMMA sims (256x128 tiles) + top-8/chunk -----
// grid (16 qb, 9 chunks), 512 threads, warp tile 64x32 (4x4 warp grid)
#define OFF_A    0                                   // 65536 (256 rows x 256B)
#define OFF_B0   65536                               // 32768
#define OFF_B1   98304                               // 32768
#define OFF_SIMS 131072                              // 256 * 65 * 4 = 66560
#define OFF_THR  (OFF_SIMS + 256 * SP_U32 * 4)       // 197632
#define OFF_TRIG (OFF_THR + 1024)                    // 198656
#define OFF_MBAR (OFF_TRIG + 1024)                   // 199680
#define SMEM_BYTES (OFF_MBAR + 64 + 1024)            // ~200.8KB

__global__ __launch_bounds__(512) void cand_kernel() {
    extern __shared__ char sraw[];
    uint32_t sb0 = smem_u32(sraw);
    uint32_t ab = (sb0 + 1023) & ~1023u;
    char* base = sraw + (ab - sb0);

    uint32_t* simsu = (uint32_t*)(base + OFF_SIMS);
    float*    thr   = (float*)(base + OFF_THR);
    int*      trig  = (int*)(base + OFF_TRIG);
    const uint32_t MB = ab + OFF_MBAR;

    const int t = threadIdx.x;
    const int w = t >> 5, lane = t & 31;
    const int wr = w >> 2, wc = w & 3;     // 4x4 warp grid
    const int m0w = wr * 64;
    const int n0w = wc * 32;
    const int q0 = blockIdx.x * TM;
    const int ck = blockIdx.y;
    const int t0 = (ck * NT_FLAT) / NCHUNK;
    const int t1 = ((ck + 1) * NT_FLAT) / NCHUNK;
    const int ntile = t1 - t0;

    float topv[CAND]; int topi[CAND];
    #pragma unroll
    for (int p = 0; p < CAND; p++) { topv[p] = NEG_INF; topi[p] = 0; }

    if (t == 0) { MBARRIER_INIT(MB, 1); MBARRIER_INIT(MB + 8, 1); }
    for (int i = t; i < TM; i += 512) { thr[i] = NEG_INF; trig[i] = 0; }

    // build swizzled query tile (256 rows)
    {
        const uint4* src = (const uint4*)(g_qh + (size_t)q0 * DIM);
        for (int i = t; i < TM * 16; i += 512) {
            int r = i >> 4, c = i & 15;
            *(uint4*)(base + OFF_A + tile_off(r, c)) = src[i];
        }
    }
    __syncthreads();

    const uint32_t A_s = ab + OFF_A;
    const uint32_t Bs_[2] = { ab + OFF_B0, ab + OFF_B1 };
    const char* tb = (const char*)g_ubsw;

    if (t == 0) {
        MBARRIER_EXPECT_TX(MB,     32768u); bulk_ld(Bs_[0], tb + ((size_t)t0 << 15),       32768u, MB);
        MBARRIER_EXPECT_TX(MB + 8, 32768u); bulk_ld(Bs_[1], tb + ((size_t)(t0 + 1) << 15), 32768u, MB + 8);
    }

    const int a_row0 = m0w + (lane & 15);
    const int b_row0 = n0w + (lane & 7) + ((lane >> 4) << 3);
    const int a_chsel = (lane >> 4);
    const int b_chsel = ((lane >> 3) & 1);

    int ph[2] = {0, 0};
    for (int i = 0; i < ntile; i++) {
        const int s = i & 1;
        const uint32_t Bs = Bs_[s];
        const int g = t0 + i;                     // global tile
        MBARRIER_WAIT_PARITY(MB + s * 8, ph[s]); ph[s] ^= 1;

        // ---- MMA: warp tile 64 rows x 32 cols, f16 accum ----
        uint32_t acc[4][4][2];
        #pragma unroll
        for (int mi = 0; mi < 4; mi++)
            #pragma unroll
            for (int nf = 0; nf < 4; nf++) { acc[mi][nf][0] = 0u; acc[mi][nf][1] = 0u; }

        #pragma unroll
        for (int k = 0; k < 8; k++) {
            uint32_t af[4][4], bf[2][4];
            #pragma unroll
            for (int mi = 0; mi < 4; mi++)
                ldsm_x4(A_s + tile_off(a_row0 + mi * 16, 2 * k + a_chsel), af[mi]);
            ldsm_x4(Bs + tile_off(b_row0,      2 * k + b_chsel), bf[0]);
            ldsm_x4(Bs + tile_off(b_row0 + 16, 2 * k + b_chsel), bf[1]);
            #pragma unroll
            for (int gg = 0; gg < 2; gg++)
                #pragma unroll
                for (int mi = 0; mi < 4; mi++) {
                    mma_f16(acc[mi][gg * 2 + 0], af[mi], bf[gg][0], bf[gg][1]);
                    mma_f16(acc[mi][gg * 2 + 1], af[mi], bf[gg][2], bf[gg][3]);
                }
        }

        // ---- per-row max + threshold trig ----
        #pragma unroll
        for (int mi = 0; mi < 4; mi++)
            #pragma unroll
            for (int h = 0; h < 2; h++) {
                __half2 m2 = *(__half2*)&acc[mi][0][h];
                #pragma unroll
                for (int nf = 1; nf < 4; nf++)
                    m2 = __hmax2(m2, *(__half2*)&acc[mi][nf][h]);
                float mx = fmaxf(__low2float(m2), __high2float(m2));
                mx = fmaxf(mx, __shfl_xor_sync(0xffffffffu, mx, 1));
                mx = fmaxf(mx, __shfl_xor_sync(0xffffffffu, mx, 2));
                int row = m0w + mi * 16 + (lane >> 2) + h * 8;
                if ((lane & 3) == 0 && mx > thr[row]) trig[row] = 1;   // benign race
            }
        __syncthreads();   // trig visible; B[s] fully consumed

        // ---- spill triggered rows (packed half2) ----
        #pragma unroll
        for (int mi = 0; mi < 4; mi++) {
            int r0 = m0w + mi * 16 + (lane >> 2);
            #pragma unroll
            for (int h = 0; h < 2; h++) {
                int row = r0 + h * 8;
                if (trig[row]) {
                    #pragma unroll
                    for (int nf = 0; nf < 4; nf++) {
                        int cp = wc * 16 + nf * 4 + (lane & 3);
                        simsu[row * SP_U32 + cp] = acc[mi][nf][h];
                    }
                }
            }
        }
        if (t == 0 && i + 2 < ntile) {
            MBARRIER_EXPECT_TX(MB + s * 8, 32768u);
            bulk_ld(Bs, tb + ((size_t)(g + 2) << 15), 32768u, MB + s * 8);
        }
        __syncthreads();   // sims visible

        // ---- owner threads (t<256) scan triggered rows ----
        if (t < TM && trig[t]) {
            int nvalid = min(TN, NU - g * TN);
            int cbase = g * TN;
            const uint32_t* srow = simsu + t * SP_U32;
            for (int cp = 0; cp * 2 < nvalid; cp++) {
                uint32_t pk = srow[cp];
                __half2 hv = *(__half2*)&pk;
                #pragma unroll
                for (int hh = 0; hh < 2; hh++) {
                    int col = cp * 2 + hh;
                    if (col >= nvalid) break;
                    float v = hh ? __high2float(hv) : __low2float(hv);
                    int idx = cbase + col;
                    if (v > topv[CAND - 1] ||
                        (v == topv[CAND - 1] && idx < topi[CAND - 1])) {
                        float vv = v; int ii = idx;
                        #pragma unroll
                        for (int p = 0; p < CAND; p++) {
                            bool better = (vv > topv[p]) || (vv == topv[p] && ii < topi[p]);
                            if (better) {
                                float tv = topv[p]; topv[p] = vv; vv = tv;
                                int   ti = topi[p]; topi[p] = ii; ii = ti;
                            }
                        }
                    }
                }
            }
            thr[t] = topv[CAND - 1];
            trig[t] = 0;
        }
        __syncthreads();
    }

    if (t < TM) {
        size_t b = (size_t)(q0 + t) * NCAND + ck * CAND;
        #pragma unroll
        for (int e = 0; e < CAND; e++) g_ci[b + e] = topi[e];
    }
}

// ---------------- Kernel C: exact rescore + select + gather -----------------
__global__ void finalize_kernel(float* __restrict__ out) {
    __shared__ float cv[NCAND];
    __shared__ int   ci[NCAND];
    __shared__ int   sel[TOPK];
    __shared__ float selv[TOPK];

    const int q = blockIdx.x;
    const int t = threadIdx.x;
    const int w = t >> 5, lane = t & 31;

    if (t < NCAND) ci[t] = g_ci[(size_t)q * NCAND + t];
    __syncthreads();

    // exact fp32 rescore: warp w handles 18 candidates
    float4 qv = *(const float4*)(g_q_n + (size_t)q * DIM + lane * 4);
    #pragma unroll 1
    for (int cc = 0; cc < 18; cc++) {
        int slot = w * 18 + cc;
        int idx = ci[slot];
        float4 uv = *(const float4*)(g_ue_n + (size_t)idx * DIM + lane * 4);
        float s = qv.x * uv.x;
        s = fmaf(qv.y, uv.y, s);
        s = fmaf(qv.z, uv.z, s);
        s = fmaf(qv.w, uv.w, s);
        #pragma unroll
        for (int o = 16; o > 0; o >>= 1) s += __shfl_xor_sync(0xffffffffu, s, o);
        if (lane == 0) cv[slot] = s;
    }
    __syncthreads();

    if (t == 0) {
        float bv[K1]; int bi[K1]; int cnt = 0;
        for (int i = 0; i < NCAND; i++) {
            float v = cv[i]; int id = ci[i];
            bool better = (cnt < K1) || (v > bv[K1 - 1]) || (v == bv[K1 - 1] && id < bi[K1 - 1]);
            if (!better) continue;
            int j = (cnt < K1) ? cnt : K1 - 1;
            while (j > 0 && (v > bv[j - 1] || (v == bv[j - 1] && id < bi[j - 1]))) {
                bv[j] = bv[j - 1]; bi[j] = bi[j - 1]; j--;
            }
            bv[j] = v; bi[j] = id;
            if (cnt < K1) cnt++;
        }
        int order[K1]; int nv = 0;
        for (int i = 0; i < K1; i++) if (bv[i] < 0.9999f) order[nv++] = i;
        int oi = nv;
        for (int i = 0; i < K1; i++) if (!(bv[i] < 0.9999f)) order[oi++] = i;
        for (int j = 0; j < TOPK; j++) {
            int pos = (nv > 0) ? order[min(j, nv - 1)] : j;
            sel[j] = bi[pos]; selv[j] = bv[pos];
        }
    }
    __syncthreads();

    float* oute = out;                              // [BQ, TOPK, DIM]
    float* outs = out + (size_t)BQ * TOPK * DIM;    // [BQ, TOPK]
    #pragma unroll
    for (int j = 0; j < TOPK; j++)
        oute[((size_t)q * TOPK + j) * DIM + t] = g_ue_n[(size_t)sel[j] * DIM + t];
    if (t < TOPK) outs[(size_t)q * TOPK + t] = selv[t];
}

// ---------------- launch ----------------------------------------------------
extern "C" void kernel_launch(void* const* d_in, const int* in_sizes, int n_in,
                              void* d_out, int out_size) {
    const float* q = (const float*)d_in[0];
    const float* u = (const float*)d_in[1];
    if (n_in >= 2 && in_sizes[0] != BQ * DIM) { const float* tmp = q; q = u; u = tmp; }
    float* out = (float*)d_out;

    int rows = NU + BQ + PADROWS;
    prep_kernel<<<(rows + 7) / 8, 256>>>(q, u);

    cudaFuncSetAttribute(cand_kernel, cudaFuncAttributeMaxDynamicSharedMemorySize, SMEM_BYTES);
    cand_kernel<<<dim3(QB, NCHUNK), 512, SMEM_BYTES>>>();

    finalize_kernel<<<BQ, DIM>>>(out);
}

// round 14
// speedup vs baseline: 2.2878x; 1.0055x over previous
#include <cuda_runtime.h>
#include <cuda_fp16.h>
#include <math.h>
#include <cstdint>

// ---------------- problem constants ----------------
#define BQ   4096
#define NU   100000
#define DIM  128
#define TOPK 5
#define K1   6
#define TM   256                       // queries per CTA
#define TN   128                       // users per tile
#define QB   (BQ / TM)                 // 16
#define NCHUNK 9                       // user-range chunks -> 144 CTAs
#define NT_FLAT 782                    // ceil(100000/128); last tile: 32 valid + 96 pad
#define PADROWS 96
#define CAND 8
#define NCAND (NCHUNK * CAND)          // 72
#define SP_U32 65                      // half2-spill pitch in u32
#define NEG_INF (-3.402823466e38f)

// ---------------- device scratch -------------------------------------------
__device__ float    g_ue_n[(size_t)NU * DIM];
__device__ float    g_q_n[(size_t)BQ * DIM];
__device__ uint32_t g_ubsw[(size_t)NT_FLAT * 8192];   // flat pre-swizzled f16 tiles (32KB each)
__device__ __half   g_qh[(size_t)BQ * DIM];
__device__ int      g_ci[(size_t)BQ * NCAND];

// ---------------- helpers ---------------------------------------------------
static __device__ __forceinline__ uint32_t smem_u32(const void* p) {
    uint32_t a;
    asm("{ .reg .u64 t; cvta.to.shared.u64 t, %1; cvt.u32.u64 %0, t; }" : "=r"(a) : "l"(p));
    return a;
}
static __device__ __forceinline__ void ldsm_x4(uint32_t addr, uint32_t r[4]) {
    asm volatile("ldmatrix.sync.aligned.m8n8.x4.shared.b16 {%0,%1,%2,%3}, [%4];"
                 : "=r"(r[0]), "=r"(r[1]), "=r"(r[2]), "=r"(r[3]) : "r"(addr));
}
static __device__ __forceinline__ void mma_f16(uint32_t c[2], const uint32_t a[4],
                                               uint32_t b0, uint32_t b1) {
    asm volatile("mma.sync.aligned.m16n8k16.row.col.f16.f16.f16.f16 "
                 "{%0,%1}, {%2,%3,%4,%5}, {%6,%7}, {%0,%1};"
                 : "+r"(c[0]), "+r"(c[1])
                 : "r"(a[0]), "r"(a[1]), "r"(a[2]), "r"(a[3]), "r"(b0), "r"(b1));
}
static __device__ __forceinline__ void bulk_ld(uint32_t dst, const void* src,
                                               uint32_t bytes, uint32_t mbar) {
    asm volatile("cp.async.bulk.shared::cluster.global.mbarrier::complete_tx::bytes "
                 "[%0], [%1], %2, [%3];"
                 :: "r"(dst), "l"(src), "r"(bytes), "r"(mbar) : "memory");
}
#define MBARRIER_INIT(addr, cnt) \
    asm volatile("mbarrier.init.shared.b64 [%0], %1;" :: "r"((uint32_t)(addr)), "r"((uint32_t)(cnt)) : "memory")
#define MBARRIER_EXPECT_TX(addr, bytes) \
    asm volatile("mbarrier.arrive.expect_tx.shared.b64 _, [%0], %1;" :: "r"((uint32_t)(addr)), "r"((uint32_t)(bytes)) : "memory")
#define MBARRIER_WAIT_PARITY(mbar_addr, parity) do { \
    uint32_t _mbar = (uint32_t)(mbar_addr); \
    uint32_t _par = (uint32_t)(parity); \
    uint32_t _done; \
    asm volatile("{\n\t.reg .pred p;\n\t" \
        "mbarrier.try_wait.parity.acquire.cta.shared::cta.b64 p, [%1], %2;\n\t" \
        "selp.b32 %0, 1, 0, p;\n\t}" : "=r"(_done) : "r"(_mbar), "r"(_par) : "memory"); \
    if (!_done) { \
        asm volatile("{\n\t.reg .pred P1;\n\t" \
            "WAIT_LOOP_%=:\n\t" \
            "mbarrier.try_wait.parity.acquire.cta.shared::cta.b64 P1, [%0], %1, 0x989680;\n\t" \
            "@P1 bra.uni WAIT_DONE_%=;\n\t" \
            "bra.uni WAIT_LOOP_%=;\n\t" \
            "WAIT_DONE_%=:\n\t}" :: "r"(_mbar), "r"(_par) : "memory"); \
    } \
} while (0)

// swizzled byte offset inside a [rows x 256B] f16 tile (16B chunks, XOR by row)
static __device__ __forceinline__ uint32_t tile_off(int r, int chunk) {
    return (uint32_t)(r * 256 + ((chunk ^ (r & 7)) << 4));
}

// ---------------- Kernel A: normalize + f16 convert into flat tiles ---------
__global__ void prep_kernel(const float* __restrict__ q, const float* __restrict__ u) {
    int row  = blockIdx.x * (blockDim.x >> 5) + (threadIdx.x >> 5);
    int lane = threadIdx.x & 31;
    int total = NU + BQ + PADROWS;
    if (row >= total) return;

    if (row >= NU + BQ) {
        int r = 32 + (row - (NU + BQ));
        size_t tbase = (size_t)(NT_FLAT - 1) << 13;
        uint32_t off = tile_off(r, lane >> 1) >> 2;
        g_ubsw[tbase + off + (lane & 1) * 2]     = 0u;
        g_ubsw[tbase + off + (lane & 1) * 2 + 1] = 0u;
        return;
    }

    const float* src;
    if (row < NU) src = u + (size_t)row * DIM;
    else          src = q + (size_t)(row - NU) * DIM;
    float4 v = *(const float4*)(src + lane * 4);
    float s = v.x * v.x + v.y * v.y + v.z * v.z + v.w * v.w;
    #pragma unroll
    for (int o = 16; o > 0; o >>= 1) s += __shfl_xor_sync(0xffffffffu, s, o);
    float inv = 1.0f / fmaxf(sqrtf(s), 1e-12f);
    float4 o4 = make_float4(v.x * inv, v.y * inv, v.z * inv, v.w * inv);

    __half2 h0 = __floats2half2_rn(o4.x, o4.y);
    __half2 h1 = __floats2half2_rn(o4.z, o4.w);
    uint32_t f0 = *(uint32_t*)&h0, f1 = *(uint32_t*)&h1;

    if (row < NU) {
        *(float4*)(g_ue_n + (size_t)row * DIM + lane * 4) = o4;
        int tile = row >> 7, n = row & 127;
        size_t tbase = (size_t)tile << 13;
        uint32_t off = tile_off(n, lane >> 1) >> 2;
        g_ubsw[tbase + off + (lane & 1) * 2]     = f0;
        g_ubsw[tbase + off + (lane & 1) * 2 + 1] = f1;
    } else {
        int r = row - NU;
        *(float4*)(g_q_n + (size_t)r * DIM + lane * 4) = o4;
        uint2 pk = make_uint2(f0, f1);
        *(uint2*)(g_qh + (size_t)r * DIM + lane * 4) = pk;
    }
}

// ---------------- Kernel B: f16 HMMA sims, 64x64 warp tiles -----------------
// grid (16 qb, 9 chunks), 256 threads (8 warps, 4x2 warp grid)
#define OFF_A    0                                   // 65536
#define OFF_B0   65536
#define OFF_B1   98304
#define OFF_SIMS 131072                              // 256 * 65 * 4 = 66560
#define OFF_THR  (OFF_SIMS + 256 * SP_U32 * 4)       // 197632
#define OFF_TRIG (OFF_THR + 1024)                    // 198656
#define OFF_MBAR (OFF_TRIG + 1024)                   // 199680
#define SMEM_BYTES (OFF_MBAR + 64 + 1024)

__global__ __launch_bounds__(256) void cand_kernel() {
    extern __shared__ char sraw[];
    uint32_t sb0 = smem_u32(sraw);
    uint32_t ab = (sb0 + 1023) & ~1023u;
    char* base = sraw + (ab - sb0);

    uint32_t* simsu = (uint32_t*)(base + OFF_SIMS);
    float*    thr   = (float*)(base + OFF_THR);
    int*      trig  = (int*)(base + OFF_TRIG);
    const uint32_t MB = ab + OFF_MBAR;

    const int t = threadIdx.x;
    const int w = t >> 5, lane = t & 31;
    const int wr = w >> 1, wc = w & 1;     // 4x2 warp grid, 64x64 tiles
    const int m0w = wr * 64;
    const int n0w = wc * 64;
    const int q0 = blockIdx.x * TM;
    const int ck = blockIdx.y;
    const int t0 = (ck * NT_FLAT) / NCHUNK;
    const int t1 = ((ck + 1) * NT_FLAT) / NCHUNK;
    const int ntile = t1 - t0;

    float topv[CAND]; int topi[CAND];
    #pragma unroll
    for (int p = 0; p < CAND; p++) { topv[p] = NEG_INF; topi[p] = 0; }

    if (t == 0) { MBARRIER_INIT(MB, 1); MBARRIER_INIT(MB + 8, 1); }
    for (int i = t; i < TM; i += 256) { thr[i] = NEG_INF; trig[i] = 0; }

    // build swizzled query tile (256 rows)
    {
        const uint4* src = (const uint4*)(g_qh + (size_t)q0 * DIM);
        for (int i = t; i < TM * 16; i += 256) {
            int r = i >> 4, c = i & 15;
            *(uint4*)(base + OFF_A + tile_off(r, c)) = src[i];
        }
    }
    __syncthreads();

    const uint32_t A_s = ab + OFF_A;
    const uint32_t Bs_[2] = { ab + OFF_B0, ab + OFF_B1 };
    const char* tb = (const char*)g_ubsw;

    if (t == 0) {
        MBARRIER_EXPECT_TX(MB,     32768u); bulk_ld(Bs_[0], tb + ((size_t)t0 << 15),       32768u, MB);
        MBARRIER_EXPECT_TX(MB + 8, 32768u); bulk_ld(Bs_[1], tb + ((size_t)(t0 + 1) << 15), 32768u, MB + 8);
    }

    const int a_row0 = m0w + (lane & 15);
    const int b_row0 = n0w + (lane & 7) + ((lane >> 4) << 3);
    const int a_chsel = (lane >> 4);
    const int b_chsel = ((lane >> 3) & 1);

    int ph[2] = {0, 0};
    for (int i = 0; i < ntile; i++) {
        const int s = i & 1;
        const uint32_t Bs = Bs_[s];
        const int g = t0 + i;
        MBARRIER_WAIT_PARITY(MB + s * 8, ph[s]); ph[s] ^= 1;

        // ---- MMA: warp tile 64 rows x 64 cols, f16 accum ----
        uint32_t acc[4][8][2];
        #pragma unroll
        for (int mi = 0; mi < 4; mi++)
            #pragma unroll
            for (int nf = 0; nf < 8; nf++) { acc[mi][nf][0] = 0u; acc[mi][nf][1] = 0u; }

        #pragma unroll
        for (int k = 0; k < 8; k++) {
            uint32_t af[4][4], bf[4][4];
            #pragma unroll
            for (int mi = 0; mi < 4; mi++)
                ldsm_x4(A_s + tile_off(a_row0 + mi * 16, 2 * k + a_chsel), af[mi]);
            #pragma unroll
            for (int gg = 0; gg < 4; gg++)
                ldsm_x4(Bs + tile_off(b_row0 + gg * 16, 2 * k + b_chsel), bf[gg]);
            #pragma unroll
            for (int gg = 0; gg < 4; gg++)
                #pragma unroll
                for (int mi = 0; mi < 4; mi++) {
                    mma_f16(acc[mi][gg * 2 + 0], af[mi], bf[gg][0], bf[gg][1]);
                    mma_f16(acc[mi][gg * 2 + 1], af[mi], bf[gg][2], bf[gg][3]);
                }
        }

        // ---- per-row max + threshold trig ----
        #pragma unroll
        for (int mi = 0; mi < 4; mi++)
            #pragma unroll
            for (int h = 0; h < 2; h++) {
                __half2 m2 = *(__half2*)&acc[mi][0][h];
                #pragma unroll
                for (int nf = 1; nf < 8; nf++)
                    m2 = __hmax2(m2, *(__half2*)&acc[mi][nf][h]);
                float mx = fmaxf(__low2float(m2), __high2float(m2));
                mx = fmaxf(mx, __shfl_xor_sync(0xffffffffu, mx, 1));
                mx = fmaxf(mx, __shfl_xor_sync(0xffffffffu, mx, 2));
                int row = m0w + mi * 16 + (lane >> 2) + h * 8;
                if ((lane & 3) == 0 && mx > thr[row]) trig[row] = 1;   // benign race
            }
        __syncthreads();   // trig visible; B[s] fully consumed

        // ---- spill triggered rows (packed half2) ----
        #pragma unroll
        for (int mi = 0; mi < 4; mi++) {
            int r0 = m0w + mi * 16 + (lane >> 2);
            #pragma unroll
            for (int h = 0; h < 2; h++) {
                int row = r0 + h * 8;
                if (trig[row]) {
                    #pragma unroll
                    for (int nf = 0; nf < 8; nf++) {
                        int cp = wc * 32 + nf * 4 + (lane & 3);
                        simsu[row * SP_U32 + cp] = acc[mi][nf][h];
                    }
                }
            }
        }
        if (t == 0 && i + 2 < ntile) {
            MBARRIER_EXPECT_TX(MB + s * 8, 32768u);
            bulk_ld(Bs, tb + ((size_t)(g + 2) << 15), 32768u, MB + s * 8);
        }
        __syncthreads();   // sims visible

        // ---- owner threads scan triggered rows (each owns one row) ----
        if (trig[t]) {
            int nvalid = min(TN, NU - g * TN);
            int cbase = g * TN;
            const uint32_t* srow = simsu + t * SP_U32;
            for (int cp = 0; cp * 2 < nvalid; cp++) {
                uint32_t pk = srow[cp];
                __half2 hv = *(__half2*)&pk;
                #pragma unroll
                for (int hh = 0; hh < 2; hh++) {
                    int col = cp * 2 + hh;
                    if (col >= nvalid) break;
                    float v = hh ? __high2float(hv) : __low2float(hv);
                    int idx = cbase + col;
                    if (v > topv[CAND - 1] ||
                        (v == topv[CAND - 1] && idx < topi[CAND - 1])) {
                        float vv = v; int ii = idx;
                        #pragma unroll
                        for (int p = 0; p < CAND; p++) {
                            bool better = (vv > topv[p]) || (vv == topv[p] && ii < topi[p]);
                            if (better) {
                                float tv = topv[p]; topv[p] = vv; vv = tv;
                                int   ti = topi[p]; topi[p] = ii; ii = ti;
                            }
                        }
                    }
                }
            }
            thr[t] = topv[CAND - 1];
            trig[t] = 0;
        }
        __syncthreads();
    }

    {
        size_t b = (size_t)(q0 + t) * NCAND + ck * CAND;
        #pragma unroll
        for (int e = 0; e < CAND; e++) g_ci[b + e] = topi[e];
    }
}

// ---------------- Kernel C: exact rescore + select + gather -----------------
__global__ void finalize_kernel(float* __restrict__ out) {
    __shared__ float cv[NCAND];
    __shared__ int   ci[NCAND];
    __shared__ int   sel[TOPK];
    __shared__ float selv[TOPK];

    const int q = blockIdx.x;
    const int t = threadIdx.x;
    const int w = t >> 5, lane = t & 31;

    if (t < NCAND) ci[t] = g_ci[(size_t)q * NCAND + t];
    __syncthreads();

    // exact fp32 rescore: warp w handles 18 candidates
    float4 qv = *(const float4*)(g_q_n + (size_t)q * DIM + lane * 4);
    #pragma unroll 1
    for (int cc = 0; cc < 18; cc++) {
        int slot = w * 18 + cc;
        int idx = ci[slot];
        float4 uv = *(const float4*)(g_ue_n + (size_t)idx * DIM + lane * 4);
        float s = qv.x * uv.x;
        s = fmaf(qv.y, uv.y, s);
        s = fmaf(qv.z, uv.z, s);
        s = fmaf(qv.w, uv.w, s);
        #pragma unroll
        for (int o = 16; o > 0; o >>= 1) s += __shfl_xor_sync(0xffffffffu, s, o);
        if (lane == 0) cv[slot] = s;
    }
    __syncthreads();

    if (t == 0) {
        float bv[K1]; int bi[K1]; int cnt = 0;
        for (int i = 0; i < NCAND; i++) {
            float v = cv[i]; int id = ci[i];
            bool better = (cnt < K1) || (v > bv[K1 - 1]) || (v == bv[K1 - 1] && id < bi[K1 - 1]);
            if (!better) continue;
            int j = (cnt < K1) ? cnt : K1 - 1;
            while (j > 0 && (v > bv[j - 1] || (v == bv[j - 1] && id < bi[j - 1]))) {
                bv[j] = bv[j - 1]; bi[j] = bi[j - 1]; j--;
            }
            bv[j] = v; bi[j] = id;
            if (cnt < K1) cnt++;
        }
        int order[K1]; int nv = 0;
        for (int i = 0; i < K1; i++) if (bv[i] < 0.9999f) order[nv++] = i;
        int oi = nv;
        for (int i = 0; i < K1; i++) if (!(bv[i] < 0.9999f)) order[oi++] = i;
        for (int j = 0; j < TOPK; j++) {
            int pos = (nv > 0) ? order[min(j, nv - 1)] : j;
            sel[j] = bi[pos]; selv[j] = bv[pos];
        }
    }
    __syncthreads();

    float* oute = out;                              // [BQ, TOPK, DIM]
    float* outs = out + (size_t)BQ * TOPK * DIM;    // [BQ, TOPK]
    #pragma unroll
    for (int j = 0; j < TOPK; j++)
        oute[((size_t)q * TOPK + j) * DIM + t] = g_ue_n[(size_t)sel[j] * DIM + t];
    if (t < TOPK) outs[(size_t)q * TOPK + t] = selv[t];
}

// ---------------- launch ----------------------------------------------------
extern "C" void kernel_launch(void* const* d_in, const int* in_sizes, int n_in,
                              void* d_out, int out_size) {
    const float* q = (const float*)d_in[0];
    const float* u = (const float*)d_in[1];
    if (n_in >= 2 && in_sizes[0] != BQ * DIM) { const float* tmp = q; q = u; u = tmp; }
    float* out = (float*)d_out;

    int rows = NU + BQ + PADROWS;
    prep_kernel<<<(rows + 7) / 8, 256>>>(q, u);

    cudaFuncSetAttribute(cand_kernel, cudaFuncAttributeMaxDynamicSharedMemorySize, SMEM_BYTES);
    cand_kernel<<<dim3(QB, NCHUNK), 256, SMEM_BYTES>>>();

    finalize_kernel<<<BQ, DIM>>>(out);
}